// round 1
// baseline (speedup 1.0000x reference)
#include <cuda_runtime.h>
#include <cuda_bf16.h>
#include <cstdint>

// Problem: content-addressed select.
//   x:              [16384, 4096] f32   (d_in[0])
//   fingerprints:   [6, 4]        f32   (d_in[1])
//   cached_outputs: [6, 16384, 4096] f32 (d_in[2])
//   out = cached_outputs[idx], idx = first i with fingerprints[i] == x[0..3], else 0.
//
// HBM-bound: 256 MiB read + 256 MiB write. Streaming float4 copy, evict-first.

static constexpr long long SLAB_ELEMS = 16384LL * 4096LL;   // 67,108,864 floats
static constexpr long long N4         = SLAB_ELEMS / 4;     // 16,777,216 float4
static constexpr int       N_CASES    = 6;

static constexpr int THREADS      = 256;
static constexpr int ITERS        = 8;                       // float4 per thread
static constexpr long long TOTAL_THREADS = N4 / ITERS;       // 2,097,152
static constexpr int BLOCKS       = (int)(TOTAL_THREADS / THREADS); // 8192

__device__ __forceinline__ int select_idx(const float* __restrict__ x,
                                          const float* __restrict__ fp) {
    // Probe = first 4 floats of x. Broadcast loads — L2/L1 hit for all threads.
    const float p0 = __ldg(&x[0]);
    const float p1 = __ldg(&x[1]);
    const float p2 = __ldg(&x[2]);
    const float p3 = __ldg(&x[3]);
    int idx = 0;
    // Reverse iteration: the LOWEST matching index wins (last write), matching
    // jnp.argmax(first True). No match leaves idx = 0.
    #pragma unroll
    for (int i = N_CASES - 1; i >= 0; --i) {
        const float f0 = __ldg(&fp[i * 4 + 0]);
        const float f1 = __ldg(&fp[i * 4 + 1]);
        const float f2 = __ldg(&fp[i * 4 + 2]);
        const float f3 = __ldg(&fp[i * 4 + 3]);
        if (f0 == p0 && f1 == p1 && f2 == p2 && f3 == p3) idx = i;
    }
    return idx;
}

__global__ __launch_bounds__(THREADS)
void cache_select_copy_kernel(const float* __restrict__ x,
                              const float* __restrict__ fingerprints,
                              const float4* __restrict__ cached,
                              float4* __restrict__ out) {
    const int idx = select_idx(x, fingerprints);
    const float4* __restrict__ src = cached + (long long)idx * N4;

    const long long tid    = (long long)blockIdx.x * THREADS + threadIdx.x;
    const long long stride = (long long)BLOCKS * THREADS;

    // Fixed trip count -> ptxas front-batches 8 independent LDG.128 (MLP=8).
    #pragma unroll
    for (int it = 0; it < ITERS; ++it) {
        const long long i = tid + (long long)it * stride;
        float4 v = __ldcs(&src[i]);   // evict-first: 256 MiB stream, no reuse
        __stcs(&out[i], v);
    }
}

extern "C" void kernel_launch(void* const* d_in, const int* in_sizes, int n_in,
                              void* d_out, int out_size) {
    const float*  x      = (const float*)d_in[0];
    const float*  fps    = (const float*)d_in[1];
    const float4* cached = (const float4*)d_in[2];
    float4*       out    = (float4*)d_out;

    cache_select_copy_kernel<<<BLOCKS, THREADS>>>(x, fps, cached, out);
}